// round 15
// baseline (speedup 1.0000x reference)
#include <cuda_runtime.h>
#include <cuda_bf16.h>

// Problem constants: T=64, B=512, H=512.
#define T_DIM 64
#define B_DIM 512
#define H4    128                    // float4 per full row
#define STRIDE (B_DIM * H4)          // float4 stride between consecutive t

// Grid: 2048 blocks x 128 threads. Block (b, quarter of H) covers lane b and
// 32 of the 128 float4 columns.
// Phase 1 (parallel):
//   P[t] = prefix_sum(ops)[t]  (P[-1] = 0)
//   src[t] = -1 if P[t]==0 else max{ u<=t : P[u-1]==P[t]-1 }
// then s_ptr[t] = source-row base pointer (init row or input row for lane b).
// Phase 2: pure streaming copy — LDS.64 ptr, LDG.128, STG.128; no branches.
__global__ void __launch_bounds__(128, 16) fused_kernel(
    const float4* __restrict__ inputs,   // (T,B,H) as float4
    const float4* __restrict__ init_h,   // (H,)    as float4
    const int*    __restrict__ ops,      // (T,B)
    float4*       __restrict__ out)      // (T,B,H) as float4
{
    __shared__ int s_P[T_DIM + 1];             // s_P[u] = P[u-1], s_P[0] = 0
    __shared__ const float4* s_ptr[T_DIM];     // per-t source row base (lane b)
    __shared__ int s_w0;

    const int bid = blockIdx.x;
    const int b   = bid >> 2;
    const int q   = bid & 3;
    const int tid = threadIdx.x;

    // ---- Phase 1a: two-warp inclusive scan of ops column b ----
    int p = 0;
    if (tid < T_DIM) {
        p = ops[tid * B_DIM + b];
        #pragma unroll
        for (int d = 1; d < 32; d <<= 1) {
            int n = __shfl_up_sync(0xFFFFFFFFu, p, d);
            if ((tid & 31) >= d) p += n;
        }
        if (tid == 31) s_w0 = p;
        if (tid == 0)  s_P[0] = 0;
    }
    __syncthreads();
    if (tid >= 32 && tid < T_DIM) p += s_w0;
    if (tid < T_DIM) s_P[tid + 1] = p;
    __syncthreads();

    // ---- Phase 1b: backward search for writer; build pointer table ----
    if (tid < T_DIM) {
        int Pt  = s_P[tid + 1];
        int src = -1;
        if (Pt > 0) {
            int target = Pt - 1;
            #pragma unroll 1
            for (int u = tid; u >= 0; --u) {
                if (s_P[u] == target) { src = u; break; }
            }
        }
        s_ptr[tid] = (src < 0)
                   ? init_h
                   : inputs + (unsigned)src * STRIDE + (unsigned)b * H4;
    }
    __syncthreads();

    // ---- Phase 2: streaming copy (64 t x 32 h4 per block) ----
    const int h4 = (q << 5) + (tid & 31);      // this thread's float4 column
    const int t0 = tid >> 5;                   // 0..3; t = t0 + 4*i
    float4* __restrict__ out_base = out + (unsigned)b * H4 + h4;

    #pragma unroll
    for (int i = 0; i < 16; i += 4) {
        const float4* a0 = s_ptr[t0 + (i + 0) * 4];
        const float4* a1 = s_ptr[t0 + (i + 1) * 4];
        const float4* a2 = s_ptr[t0 + (i + 2) * 4];
        const float4* a3 = s_ptr[t0 + (i + 3) * 4];
        float4 v0 = __ldg(a0 + h4);
        float4 v1 = __ldg(a1 + h4);
        float4 v2 = __ldg(a2 + h4);
        float4 v3 = __ldg(a3 + h4);
        out_base[(unsigned)(t0 + (i + 0) * 4) * STRIDE] = v0;
        out_base[(unsigned)(t0 + (i + 1) * 4) * STRIDE] = v1;
        out_base[(unsigned)(t0 + (i + 2) * 4) * STRIDE] = v2;
        out_base[(unsigned)(t0 + (i + 3) * 4) * STRIDE] = v3;
    }
}

extern "C" void kernel_launch(void* const* d_in, const int* in_sizes, int n_in,
                              void* d_out, int out_size) {
    const float* inputs = (const float*)d_in[0];   // (T,B,H) f32
    const float* init_h = (const float*)d_in[1];   // (H,)    f32
    const int*   ops    = (const int*)d_in[2];     // (T,B)   i32
    float* out = (float*)d_out;                    // (T,B,H) f32

    fused_kernel<<<4 * B_DIM, 128>>>(
        (const float4*)inputs, (const float4*)init_h, ops, (float4*)out);
}

// round 16
// speedup vs baseline: 1.4877x; 1.4877x over previous
#include <cuda_runtime.h>
#include <cuda_bf16.h>

// Problem constants: T=64, B=512, H=512.
#define T_DIM 64
#define B_DIM 512
#define H4    128                    // float4 per full row
#define STRIDE (B_DIM * H4)          // float4 stride between consecutive t

// Grid: 1024 blocks x 128 threads. Block (b, half of H). Each thread owns TWO
// float4 columns (h4, h4+32) so one warp-uniform s_src read feeds 2 LDG.128
// + 2 STG.128 (fewer LSU ops per byte than one column per thread).
// Phase 1 (parallel, proven):
//   P[t] = prefix_sum(ops)[t]  (P[-1] = 0)
//   src[t] = -1 if P[t]==0 else max{ u<=t : P[u-1]==P[t]-1 }
__global__ void __launch_bounds__(128, 12) fused_kernel(
    const float4* __restrict__ inputs,   // (T,B,H) as float4
    const float4* __restrict__ init_h,   // (H,)    as float4
    const int*    __restrict__ ops,      // (T,B)
    float4*       __restrict__ out)      // (T,B,H) as float4
{
    __shared__ int s_P[T_DIM + 1];       // s_P[u] = P[u-1], s_P[0] = 0
    __shared__ int s_src[T_DIM];
    __shared__ int s_w0;

    const int bid  = blockIdx.x;
    const int b    = bid >> 1;
    const int half = bid & 1;
    const int tid  = threadIdx.x;

    // ---- Phase 1a: two-warp inclusive scan of ops column b ----
    int p = 0;
    if (tid < T_DIM) {
        p = ops[tid * B_DIM + b];
        #pragma unroll
        for (int d = 1; d < 32; d <<= 1) {
            int n = __shfl_up_sync(0xFFFFFFFFu, p, d);
            if ((tid & 31) >= d) p += n;
        }
        if (tid == 31) s_w0 = p;
        if (tid == 0)  s_P[0] = 0;
    }
    __syncthreads();
    if (tid >= 32 && tid < T_DIM) p += s_w0;
    if (tid < T_DIM) s_P[tid + 1] = p;
    __syncthreads();

    // ---- Phase 1b: per-t backward search for the matching writer ----
    if (tid < T_DIM) {
        int Pt  = s_P[tid + 1];
        int src = -1;
        if (Pt > 0) {
            int target = Pt - 1;
            #pragma unroll 1
            for (int u = tid; u >= 0; --u) {
                if (s_P[u] == target) { src = u; break; }
            }
        }
        s_src[tid] = src;
    }
    __syncthreads();

    // ---- Phase 2: streaming copy, 2 columns x 16 t per thread ----
    const int c   = tid & 31;                    // column within half-group
    const int tr  = tid >> 5;                    // 0..3; t = tr + 4*i
    const int h4a = (half << 6) + c;             // first column
    const float4* __restrict__ in_a  = inputs + (unsigned)b * H4 + h4a;
    float4*       __restrict__ out_a = out    + (unsigned)b * H4 + h4a;
    const float4 vinit_a = init_h[h4a];
    const float4 vinit_b = init_h[h4a + 32];

    #pragma unroll
    for (int i = 0; i < 16; i += 2) {
        const int ta = tr + (i << 2);            // tr + 4*i
        const int tb = ta + 4;
        const int s0 = s_src[ta];
        const int s1 = s_src[tb];
        float4 va0 = vinit_a, vb0 = vinit_b;
        float4 va1 = vinit_a, vb1 = vinit_b;
        if (s0 >= 0) {
            const float4* a = in_a + (unsigned)s0 * STRIDE;
            va0 = __ldg(a);
            vb0 = __ldg(a + 32);
        }
        if (s1 >= 0) {
            const float4* a = in_a + (unsigned)s1 * STRIDE;
            va1 = __ldg(a);
            vb1 = __ldg(a + 32);
        }
        float4* d0 = out_a + (unsigned)ta * STRIDE;
        float4* d1 = out_a + (unsigned)tb * STRIDE;
        d0[0]  = va0;
        d0[32] = vb0;
        d1[0]  = va1;
        d1[32] = vb1;
    }
}

extern "C" void kernel_launch(void* const* d_in, const int* in_sizes, int n_in,
                              void* d_out, int out_size) {
    const float* inputs = (const float*)d_in[0];   // (T,B,H) f32
    const float* init_h = (const float*)d_in[1];   // (H,)    f32
    const int*   ops    = (const int*)d_in[2];     // (T,B)   i32
    float* out = (float*)d_out;                    // (T,B,H) f32

    fused_kernel<<<2 * B_DIM, 128>>>(
        (const float4*)inputs, (const float4*)init_h, ops, (float4*)out);
}